// round 12
// baseline (speedup 1.0000x reference)
#include <cuda_runtime.h>
#include <cstdint>
#include <cstddef>
#include <climits>

#define NPTS     8192
#define BATCH    8
#define MSEL     4096        // ceil(0.5 * 8192)
#define NTHREADS 512
#define NWARPS   16
#define PPT      16          // points per thread
#define NPAIR    8           // f32x2 pairs per thread

// smem floats: raw pts [NPTS*3] + sort keys [NPTS] + wmax [2*16] + widx [2*16] + idx [MSEL]
#define S_PTS   0
#define S_SORT  (NPTS * 3)
#define S_WMAX  (NPTS * 3 + NPTS)
#define S_WIDX  (NPTS * 3 + NPTS + 32)
#define S_IDX   (NPTS * 3 + NPTS + 64)
#define SMEM_FLOATS (NPTS * 3 + NPTS + 64 + MSEL)
#define SMEM_BYTES  (SMEM_FLOATS * 4)

__device__ int g_sel_idx[BATCH * MSEL];

// ---------------- f32x2 packed helpers (sm_100+) ----------------
__device__ __forceinline__ unsigned long long pack2(float lo, float hi) {
    unsigned long long r;
    asm("mov.b64 %0, {%1, %2};" : "=l"(r) : "f"(lo), "f"(hi));
    return r;
}
__device__ __forceinline__ void unpack2(unsigned long long v, float& lo, float& hi) {
    asm("mov.b64 {%0, %1}, %2;" : "=f"(lo), "=f"(hi) : "l"(v));
}
__device__ __forceinline__ unsigned long long add2(unsigned long long a, unsigned long long b) {
    unsigned long long r;
    asm("add.rn.f32x2 %0, %1, %2;" : "=l"(r) : "l"(a), "l"(b));
    return r;
}
__device__ __forceinline__ unsigned long long mul2(unsigned long long a, unsigned long long b) {
    unsigned long long r;
    asm("mul.rn.f32x2 %0, %1, %2;" : "=l"(r) : "l"(a), "l"(b));
    return r;
}

__device__ __forceinline__ unsigned spread6(unsigned v) {
    // 6 bits -> bits 0,3,6,9,12,15
    return (v & 1u) | ((v & 2u) << 2) | ((v & 4u) << 4) |
           ((v & 8u) << 6) | ((v & 16u) << 8) | ((v & 32u) << 10);
}

extern __shared__ float smem[];

// ---------------- FPS kernel: one CTA (512 thr) per batch ----------------
__global__ __launch_bounds__(NTHREADS, 1)
void fps_kernel(const float* __restrict__ points, float* __restrict__ dp_out)
{
    float*    s_pts  = smem + S_PTS;              // [NPTS*3] xyz by ORIGINAL index
    unsigned* s_sort = (unsigned*)(smem + S_SORT);// [NPTS] (morton<<13)|origidx
    unsigned* s_wmax = (unsigned*)(smem + S_WMAX);// [2][16]
    int*      s_widx = (int*)(smem + S_WIDX);     // [2][16]
    int*      s_idx  = (int*)(smem + S_IDX);      // [MSEL] (original indices)

    const int b    = blockIdx.x;
    const int tid  = threadIdx.x;
    const int lane = tid & 31;
    const int warp = tid >> 5;                    // 0..15
    const float* p = points + (size_t)b * NPTS * 3;

    // Stage raw points to shared (coalesced).
    for (int k = tid; k < NPTS * 3; k += NTHREADS) s_pts[k] = p[k];
    __syncthreads();

    // Morton keys: 6 bits/axis over [-6,6] (clamped; heuristic only).
    for (int i = tid; i < NPTS; i += NTHREADS) {
        float x = s_pts[3 * i + 0], y = s_pts[3 * i + 1], z = s_pts[3 * i + 2];
        unsigned ix = (unsigned)min(63, max(0, (int)((x + 6.0f) * (64.0f / 12.0f))));
        unsigned iy = (unsigned)min(63, max(0, (int)((y + 6.0f) * (64.0f / 12.0f))));
        unsigned iz = (unsigned)min(63, max(0, (int)((z + 6.0f) * (64.0f / 12.0f))));
        unsigned code = (spread6(ix) << 2) | (spread6(iy) << 1) | spread6(iz);
        s_sort[i] = (code << 13) | (unsigned)i;
    }

    // Bitonic sort (ascending) of the 8192 keys.
    for (int k = 2; k <= NPTS; k <<= 1) {
        for (int j = k >> 1; j > 0; j >>= 1) {
            __syncthreads();
            for (int t = tid; t < NPTS; t += NTHREADS) {
                int ixj = t ^ j;
                if (ixj > t) {
                    unsigned a = s_sort[t], c = s_sort[ixj];
                    bool up = ((t & k) == 0);
                    if ((a > c) == up) { s_sort[t] = c; s_sort[ixj] = a; }
                }
            }
        }
    }
    __syncthreads();

    // Register gather by sorted position: warp w owns sorted [512w, 512w+512).
    // pair j: lo = sorted(512w + 64j + lane), hi = sorted(512w + 64j + 32 + lane).
    unsigned long long NX[NPAIR], NY[NPAIR], NZ[NPAIR];
    unsigned oidx[NPAIR];           // packed original indices: lo | (hi<<16)
    float mind[PPT];
    float mnx = 1e30f, mny = 1e30f, mnz = 1e30f;
    float mxx = -1e30f, mxy = -1e30f, mxz = -1e30f;
#pragma unroll
    for (int i = 0; i < PPT; i++) mind[i] = 1e10f;
    const int wbase = warp * 512;
#pragma unroll
    for (int j = 0; j < NPAIR; j++) {
        int o0 = (int)(s_sort[wbase + 64 * j + lane] & 0x1FFFu);
        int o1 = (int)(s_sort[wbase + 64 * j + 32 + lane] & 0x1FFFu);
        float x0 = s_pts[3 * o0 + 0], y0 = s_pts[3 * o0 + 1], z0 = s_pts[3 * o0 + 2];
        float x1 = s_pts[3 * o1 + 0], y1 = s_pts[3 * o1 + 1], z1 = s_pts[3 * o1 + 2];
        NX[j] = pack2(-x0, -x1);
        NY[j] = pack2(-y0, -y1);
        NZ[j] = pack2(-z0, -z1);
        oidx[j] = (unsigned)o0 | ((unsigned)o1 << 16);
        mnx = fminf(mnx, fminf(x0, x1)); mxx = fmaxf(mxx, fmaxf(x0, x1));
        mny = fminf(mny, fminf(y0, y1)); mxy = fmaxf(mxy, fmaxf(y0, y1));
        mnz = fminf(mnz, fminf(z0, z1)); mxz = fmaxf(mxz, fmaxf(z0, z1));
    }
    // Warp bounding box -> sphere (conservative radius).
#pragma unroll
    for (int off = 16; off > 0; off >>= 1) {
        mnx = fminf(mnx, __shfl_xor_sync(0xffffffffu, mnx, off));
        mny = fminf(mny, __shfl_xor_sync(0xffffffffu, mny, off));
        mnz = fminf(mnz, __shfl_xor_sync(0xffffffffu, mnz, off));
        mxx = fmaxf(mxx, __shfl_xor_sync(0xffffffffu, mxx, off));
        mxy = fmaxf(mxy, __shfl_xor_sync(0xffffffffu, mxy, off));
        mxz = fmaxf(mxz, __shfl_xor_sync(0xffffffffu, mxz, off));
    }
    const float cx = (mnx + mxx) * 0.5f;
    const float cy = (mny + mxy) * 0.5f;
    const float cz = (mnz + mxz) * 0.5f;
    float ex = mxx - mnx, ey = mxy - mny, ez = mxz - mnz;
    const float rad = sqrtf(ex * ex + ey * ey + ez * ez) * 0.5f * 1.0002f + 1e-6f;

    if (tid == 0) s_idx[0] = 0;
    __syncthreads();

    int gidx = 0;            // current selected ORIGINAL index
    int buf  = 0;
    unsigned wmax_c = __float_as_uint(1e10f);  // cached warp max (valid: minds all 1e10)
    int      widx_c = 0;                       // don't-care until first active iter

    for (int step = 1; step < MSEL; ++step) {
        float qx = s_pts[3 * gidx + 0];
        float qy = s_pts[3 * gidx + 1];
        float qz = s_pts[3 * gidx + 2];

        // Warp-uniform prune test: can q update ANY mind in this warp's chunk?
        float dcx = qx - cx, dcy = qy - cy, dcz = qz - cz;
        float qc2 = dcx * dcx + dcy * dcy + dcz * dcz;
        float thr = rad + sqrtf(__uint_as_float(wmax_c)) * 1.001f;
        if (!(qc2 > thr * thr)) {
            // Active: exact update, XLA op-for-op: ((dx*dx + dy*dy) + dz*dz).
            unsigned long long qx2 = pack2(qx, qx);
            unsigned long long qy2 = pack2(qy, qy);
            unsigned long long qz2 = pack2(qz, qz);
#pragma unroll
            for (int j = 0; j < NPAIR; j++) {
                unsigned long long dx = add2(NX[j], qx2);
                unsigned long long dy = add2(NY[j], qy2);
                unsigned long long dz = add2(NZ[j], qz2);
                unsigned long long sx = mul2(dx, dx);
                unsigned long long sy = mul2(dy, dy);
                unsigned long long sz = mul2(dz, dz);
                unsigned long long dd = add2(add2(sx, sy), sz);
                float d0, d1;
                unpack2(dd, d0, d1);
                mind[2 * j]     = fminf(mind[2 * j], d0);
                mind[2 * j + 1] = fminf(mind[2 * j + 1], d1);
            }
            float t0 = fmaxf(fmaxf(mind[0],  mind[1]),  fmaxf(mind[2],  mind[3]));
            float t1 = fmaxf(fmaxf(mind[4],  mind[5]),  fmaxf(mind[6],  mind[7]));
            float t2 = fmaxf(fmaxf(mind[8],  mind[9]),  fmaxf(mind[10], mind[11]));
            float t3 = fmaxf(fmaxf(mind[12], mind[13]), fmaxf(mind[14], mind[15]));
            float vmax = fmaxf(fmaxf(t0, t1), fmaxf(t2, t3));

            unsigned vb   = __float_as_uint(vmax);
            unsigned wmax = __reduce_max_sync(0xffffffffu, vb);
            int cand = INT_MAX;
            if (vb == wmax) {
                // lowest ORIGINAL index among thread-local ties
#pragma unroll
                for (int i = 0; i < PPT; i++)
                    if (__float_as_uint(mind[i]) == vb) {
                        int og = (int)((oidx[i >> 1] >> ((i & 1) * 16)) & 0xFFFFu);
                        cand = min(cand, og);
                    }
            }
            widx_c = __reduce_min_sync(0xffffffffu, cand);
            wmax_c = wmax;
        }
        // (skipped warps: cached wmax_c/widx_c still exact — minds unchanged)
        if (lane == 0) {
            s_wmax[buf * 16 + warp] = wmax_c;
            s_widx[buf * 16 + warp] = widx_c;
        }
        __syncthreads();  // single barrier per iteration

        // Stage B: every warp redundantly reduces across the 16 warp results.
        unsigned wv   = s_wmax[buf * 16 + (lane & 15)];
        unsigned gmax = __reduce_max_sync(0xffffffffu, wv);
        int c2 = (wv == gmax) ? s_widx[buf * 16 + (lane & 15)] : INT_MAX;
        gidx   = __reduce_min_sync(0xffffffffu, c2);

        if (tid == 0) s_idx[step] = gidx;
        buf ^= 1;
    }
    __syncthreads();

    // Batched writeout of indices + selected points.
    for (int r = tid; r < MSEL; r += NTHREADS) {
        int id = s_idx[r];
        g_sel_idx[b * MSEL + r] = id;
        size_t o = ((size_t)b * MSEL + r) * 3;
        dp_out[o + 0] = s_pts[3 * id + 0];
        dp_out[o + 1] = s_pts[3 * id + 1];
        dp_out[o + 2] = s_pts[3 * id + 2];
    }
}

// ---------------- Feature gather: [B, m, 256] float32 ----------------
__global__ void gather_kernel(const float* __restrict__ feat, float* __restrict__ df_out)
{
    int r = blockIdx.x * 4 + (threadIdx.x >> 6);
    int c = threadIdx.x & 63;
    int b = r >> 12;
    int id = g_sel_idx[r];
    const float4* src = (const float4*)(feat + ((size_t)b * NPTS + id) * 256);
    float4 v = src[c];
    ((float4*)df_out)[(size_t)r * 64 + c] = v;
}

extern "C" void kernel_launch(void* const* d_in, const int* in_sizes, int n_in,
                              void* d_out, int out_size)
{
    (void)n_in; (void)out_size;
    const float* points;
    const float* feats;
    if (in_sizes[0] == BATCH * NPTS * 3) {
        points = (const float*)d_in[0];
        feats  = (const float*)d_in[1];
    } else {
        points = (const float*)d_in[1];
        feats  = (const float*)d_in[0];
    }

    float* out = (float*)d_out;
    float* dp  = out;                              // [B, m, 3]
    float* df  = out + (size_t)BATCH * MSEL * 3;   // [B, m, 256]

    cudaFuncSetAttribute(fps_kernel, cudaFuncAttributeMaxDynamicSharedMemorySize,
                         SMEM_BYTES);
    fps_kernel<<<BATCH, NTHREADS, SMEM_BYTES>>>(points, dp);
    gather_kernel<<<(BATCH * MSEL) / 4, 256>>>(feats, df);
}

// round 14
// speedup vs baseline: 1.0170x; 1.0170x over previous
#include <cuda_runtime.h>
#include <cstdint>
#include <cstddef>
#include <climits>

#define NPTS     8192
#define BATCH    8
#define MSEL     4096        // ceil(0.5 * 8192)
#define NTHREADS 512
#define PPT      16          // points per thread
#define NPAIR    8           // f32x2 pairs per thread
// smem floats: packed pos pairs [NPTS*6] + fused warp results [2*16 u64 = 64 floats] + idx list [MSEL]
#define SMEM_FLOATS (NPTS * 6 + 64 + MSEL)
#define SMEM_BYTES  (SMEM_FLOATS * 4)

// Selected indices, produced by FPS kernel, consumed by gather kernel.
__device__ int g_sel_idx[BATCH * MSEL];

// ---------------- f32x2 packed helpers (sm_100+) ----------------
__device__ __forceinline__ unsigned long long pack2(float lo, float hi) {
    unsigned long long r;
    asm("mov.b64 %0, {%1, %2};" : "=l"(r) : "f"(lo), "f"(hi));
    return r;
}
__device__ __forceinline__ void unpack2(unsigned long long v, float& lo, float& hi) {
    asm("mov.b64 {%0, %1}, %2;" : "=f"(lo), "=f"(hi) : "l"(v));
}
__device__ __forceinline__ unsigned long long add2(unsigned long long a, unsigned long long b) {
    unsigned long long r;
    asm("add.rn.f32x2 %0, %1, %2;" : "=l"(r) : "l"(a), "l"(b));
    return r;
}
__device__ __forceinline__ unsigned long long mul2(unsigned long long a, unsigned long long b) {
    unsigned long long r;
    asm("mul.rn.f32x2 %0, %1, %2;" : "=l"(r) : "l"(a), "l"(b));
    return r;
}

extern __shared__ float smem[];

// ---------------- FPS kernel: one CTA (512 thr) per batch ----------------
__global__ __launch_bounds__(NTHREADS, 1)
void fps_kernel(const float* __restrict__ points, float* __restrict__ dp_out)
{
    float*              s_pos2 = smem;                                  // [NPTS*6]
    unsigned long long* s_comb = (unsigned long long*)(smem + NPTS * 6);// [2][16] (wmax<<32)|widx
    int*                s_idx  = (int*)(smem + NPTS * 6 + 64);          // [MSEL]

    const int b    = blockIdx.x;
    const int tid  = threadIdx.x;
    const int lane = tid & 31;
    const int warp = tid >> 5;                        // 0..15
    const float* p = points + (size_t)b * NPTS * 3;

    // Stage duplicated point pairs to shared (coalesced gmem reads).
    for (int k = tid; k < NPTS * 3; k += NTHREADS) {
        float v = p[k];
        int   i = k / 3, c = k - 3 * i;
        s_pos2[6 * i + 2 * c]     = v;
        s_pos2[6 * i + 2 * c + 1] = v;
    }
    if (tid == 0) s_idx[0] = 0;
    __syncthreads();

    // Register-resident NEGATED coords: pair j holds ids (2j)*512+tid (lo), (2j+1)*512+tid (hi).
    unsigned long long NX[NPAIR], NY[NPAIR], NZ[NPAIR];
    float mind[PPT];
#pragma unroll
    for (int i = 0; i < PPT; i++) mind[i] = 1e10f;
#pragma unroll
    for (int j = 0; j < NPAIR; j++) {
        int i0 = (2 * j) * NTHREADS + tid;
        int i1 = (2 * j + 1) * NTHREADS + tid;
        NX[j] = pack2(-s_pos2[6 * i0 + 0], -s_pos2[6 * i1 + 0]);
        NY[j] = pack2(-s_pos2[6 * i0 + 2], -s_pos2[6 * i1 + 2]);
        NZ[j] = pack2(-s_pos2[6 * i0 + 4], -s_pos2[6 * i1 + 4]);
    }

    int gidx = 0;  // step 0: deterministic start at index 0
    int buf  = 0;

    for (int step = 1; step < MSEL; ++step) {
        // Broadcast the selected point as pre-duplicated 64-bit pairs (3x LDS.64).
        const unsigned long long* lp =
            (const unsigned long long*)(s_pos2 + 6 * gidx);
        unsigned long long lx2 = lp[0];
        unsigned long long ly2 = lp[1];
        unsigned long long lz2 = lp[2];

        // XLA-exact: (-x + lx)^2 == (x - lx)^2 bit-exactly; every op rounded, no FMA.
#pragma unroll
        for (int j = 0; j < NPAIR; j++) {
            unsigned long long dx = add2(NX[j], lx2);
            unsigned long long dy = add2(NY[j], ly2);
            unsigned long long dz = add2(NZ[j], lz2);
            unsigned long long sx = mul2(dx, dx);
            unsigned long long sy = mul2(dy, dy);
            unsigned long long sz = mul2(dz, dz);
            unsigned long long dd = add2(add2(sx, sy), sz);
            float d0, d1;
            unpack2(dd, d0, d1);
            mind[2 * j]     = fminf(mind[2 * j], d0);
            mind[2 * j + 1] = fminf(mind[2 * j + 1], d1);
        }

        // Max-tree over the 16 running minima (depth 4).
        float t0 = fmaxf(fmaxf(mind[0],  mind[1]),  fmaxf(mind[2],  mind[3]));
        float t1 = fmaxf(fmaxf(mind[4],  mind[5]),  fmaxf(mind[6],  mind[7]));
        float t2 = fmaxf(fmaxf(mind[8],  mind[9]),  fmaxf(mind[10], mind[11]));
        float t3 = fmaxf(fmaxf(mind[12], mind[13]), fmaxf(mind[14], mind[15]));
        float vmax = fmaxf(fmaxf(t0, t1), fmaxf(t2, t3));

        // Stage A: warp max value; tied threads find their lowest index via a
        // depth-4 min-tree (short serial chain), then warp min-index REDUX.
        unsigned vb   = __float_as_uint(vmax);  // nonneg floats: uint order == float order
        unsigned wmax = __reduce_max_sync(0xffffffffu, vb);
        int cand = INT_MAX;
        if (vb == wmax) {
            int c[PPT];
#pragma unroll
            for (int i = 0; i < PPT; i++)
                c[i] = (__float_as_uint(mind[i]) == vb) ? (i * NTHREADS + tid) : INT_MAX;
#pragma unroll
            for (int s = PPT / 2; s > 0; s >>= 1)
#pragma unroll
                for (int i = 0; i < PPT / 2; i++)
                    if (i < s) c[i] = min(c[i], c[i + s]);
            cand = c[0];
        }
        int wmin_idx = __reduce_min_sync(0xffffffffu, cand);

        // Fused per-warp result: one STS.64.
        if (lane == 0)
            s_comb[buf * 16 + warp] =
                ((unsigned long long)wmax << 32) | (unsigned)wmin_idx;
        __syncthreads();  // single barrier per iteration

        // Stage B: every warp redundantly reduces across the 16 warp results.
        // Lanes 16..31 mirror lanes 0..15 (same data) — harmless for max/min.
        unsigned long long cv = s_comb[buf * 16 + (lane & 15)];
        unsigned wv   = (unsigned)(cv >> 32);
        unsigned gmax = __reduce_max_sync(0xffffffffu, wv);
        int c2 = (wv == gmax) ? (int)(unsigned)cv : INT_MAX;
        gidx   = __reduce_min_sync(0xffffffffu, c2);

        if (tid == 0) s_idx[step] = gidx;   // 1 predicated STS
        buf ^= 1;                           // double-buffer: next step uses other slots
    }
    __syncthreads();  // s_idx complete

    // Batched writeout of indices + selected points (off the critical loop).
    for (int r = tid; r < MSEL; r += NTHREADS) {
        int id = s_idx[r];
        g_sel_idx[b * MSEL + r] = id;
        size_t o = ((size_t)b * MSEL + r) * 3;
        dp_out[o + 0] = s_pos2[6 * id + 0];
        dp_out[o + 1] = s_pos2[6 * id + 2];
        dp_out[o + 2] = s_pos2[6 * id + 4];
    }
}

// ---------------- Feature gather: [B, m, 256] float32 ----------------
__global__ void gather_kernel(const float* __restrict__ feat, float* __restrict__ df_out)
{
    // 256 threads/block -> 4 rows/block, 64 threads (float4 x 64 = 256 floats) per row.
    int r = blockIdx.x * 4 + (threadIdx.x >> 6);
    int c = threadIdx.x & 63;
    int b = r >> 12;  // r / 4096
    int id = g_sel_idx[r];
    const float4* src = (const float4*)(feat + ((size_t)b * NPTS + id) * 256);
    float4 v = src[c];
    ((float4*)df_out)[(size_t)r * 64 + c] = v;
}

extern "C" void kernel_launch(void* const* d_in, const int* in_sizes, int n_in,
                              void* d_out, int out_size)
{
    (void)n_in; (void)out_size;
    const float* points;
    const float* feats;
    if (in_sizes[0] == BATCH * NPTS * 3) {
        points = (const float*)d_in[0];
        feats  = (const float*)d_in[1];
    } else {
        points = (const float*)d_in[1];
        feats  = (const float*)d_in[0];
    }

    float* out = (float*)d_out;
    float* dp  = out;                              // [B, m, 3]
    float* df  = out + (size_t)BATCH * MSEL * 3;   // [B, m, 256]

    cudaFuncSetAttribute(fps_kernel, cudaFuncAttributeMaxDynamicSharedMemorySize,
                         SMEM_BYTES);
    fps_kernel<<<BATCH, NTHREADS, SMEM_BYTES>>>(points, dp);
    gather_kernel<<<(BATCH * MSEL) / 4, 256>>>(feats, df);
}

// round 16
// speedup vs baseline: 1.0652x; 1.0474x over previous
#include <cuda_runtime.h>
#include <cstdint>
#include <cstddef>
#include <climits>

#define NPTS     8192
#define BATCH    8
#define MSEL     4096        // ceil(0.5 * 8192)
#define NTHREADS 256
#define NWARPS   8
#define PPT      32          // points per thread
#define NPAIR    16          // f32x2 pairs per thread
// smem floats: packed pos pairs [NPTS*6] + warp max [2*8] + warp idx [2*8] + idx list [MSEL]
#define SMEM_FLOATS (NPTS * 6 + 16 + 16 + MSEL)
#define SMEM_BYTES  (SMEM_FLOATS * 4)

// Selected indices, produced by FPS kernel, consumed by gather kernel.
__device__ int g_sel_idx[BATCH * MSEL];

// ---------------- f32x2 packed helpers (sm_100+) ----------------
__device__ __forceinline__ unsigned long long pack2(float lo, float hi) {
    unsigned long long r;
    asm("mov.b64 %0, {%1, %2};" : "=l"(r) : "f"(lo), "f"(hi));
    return r;
}
__device__ __forceinline__ void unpack2(unsigned long long v, float& lo, float& hi) {
    asm("mov.b64 {%0, %1}, %2;" : "=f"(lo), "=f"(hi) : "l"(v));
}
__device__ __forceinline__ unsigned long long add2(unsigned long long a, unsigned long long b) {
    unsigned long long r;
    asm("add.rn.f32x2 %0, %1, %2;" : "=l"(r) : "l"(a), "l"(b));
    return r;
}
__device__ __forceinline__ unsigned long long mul2(unsigned long long a, unsigned long long b) {
    unsigned long long r;
    asm("mul.rn.f32x2 %0, %1, %2;" : "=l"(r) : "l"(a), "l"(b));
    return r;
}

extern __shared__ float smem[];

// ---------------- FPS kernel: one CTA (256 thr) per batch ----------------
__global__ __launch_bounds__(NTHREADS, 1)
void fps_kernel(const float* __restrict__ points, float* __restrict__ dp_out)
{
    float*    s_pos2 = smem;                          // [NPTS*6] {x,x}{y,y}{z,z} per point
    unsigned* s_wmax = (unsigned*)(smem + NPTS * 6);  // [2][8] per-warp max bits
    int*      s_widx = (int*)(smem + NPTS * 6 + 16);  // [2][8] per-warp min cand idx
    int*      s_idx  = (int*)(smem + NPTS * 6 + 32);  // [MSEL] selected indices

    const int b    = blockIdx.x;
    const int tid  = threadIdx.x;
    const int lane = tid & 31;
    const int warp = tid >> 5;                        // 0..7
    const float* p = points + (size_t)b * NPTS * 3;

    // Stage duplicated point pairs to shared (coalesced gmem reads).
    for (int k = tid; k < NPTS * 3; k += NTHREADS) {
        float v = p[k];
        int   i = k / 3, c = k - 3 * i;
        s_pos2[6 * i + 2 * c]     = v;
        s_pos2[6 * i + 2 * c + 1] = v;
    }
    if (tid == 0) s_idx[0] = 0;
    __syncthreads();

    // Register-resident NEGATED coords: pair j holds ids (2j)*256+tid (lo), (2j+1)*256+tid (hi).
    unsigned long long NX[NPAIR], NY[NPAIR], NZ[NPAIR];
    float mind[PPT];
#pragma unroll
    for (int i = 0; i < PPT; i++) mind[i] = 1e10f;
#pragma unroll
    for (int j = 0; j < NPAIR; j++) {
        int i0 = (2 * j) * NTHREADS + tid;
        int i1 = (2 * j + 1) * NTHREADS + tid;
        NX[j] = pack2(-s_pos2[6 * i0 + 0], -s_pos2[6 * i1 + 0]);
        NY[j] = pack2(-s_pos2[6 * i0 + 2], -s_pos2[6 * i1 + 2]);
        NZ[j] = pack2(-s_pos2[6 * i0 + 4], -s_pos2[6 * i1 + 4]);
    }

    int gidx = 0;  // step 0: deterministic start at index 0
    int buf  = 0;

    for (int step = 1; step < MSEL; ++step) {
        // Broadcast the selected point as pre-duplicated 64-bit pairs (3x LDS.64).
        const unsigned long long* lp =
            (const unsigned long long*)(s_pos2 + 6 * gidx);
        unsigned long long lx2 = lp[0];
        unsigned long long ly2 = lp[1];
        unsigned long long lz2 = lp[2];

        // XLA-exact: (-x + lx)^2 == (x - lx)^2 bit-exactly; every op rounded, no FMA.
#pragma unroll
        for (int j = 0; j < NPAIR; j++) {
            unsigned long long dx = add2(NX[j], lx2);
            unsigned long long dy = add2(NY[j], ly2);
            unsigned long long dz = add2(NZ[j], lz2);
            unsigned long long sx = mul2(dx, dx);
            unsigned long long sy = mul2(dy, dy);
            unsigned long long sz = mul2(dz, dz);
            unsigned long long dd = add2(add2(sx, sy), sz);
            float d0, d1;
            unpack2(dd, d0, d1);
            mind[2 * j]     = fminf(mind[2 * j], d0);
            mind[2 * j + 1] = fminf(mind[2 * j + 1], d1);
        }

        // Max-tree over the 32 running minima (depth 5).
        float u[8];
#pragma unroll
        for (int g = 0; g < 8; g++)
            u[g] = fmaxf(fmaxf(mind[4 * g], mind[4 * g + 1]),
                         fmaxf(mind[4 * g + 2], mind[4 * g + 3]));
        float vmax = fmaxf(fmaxf(fmaxf(u[0], u[1]), fmaxf(u[2], u[3])),
                           fmaxf(fmaxf(u[4], u[5]), fmaxf(u[6], u[7])));

        // Stage A: warp max value + lowest tied index within warp.
        // 4 interleaved 8-deep SEL chains (short serial depth), exact lowest-index.
        unsigned vb   = __float_as_uint(vmax);  // nonneg floats: uint order == float order
        unsigned wmax = __reduce_max_sync(0xffffffffu, vb);
        int cand = INT_MAX;
        if (vb == wmax) {
            int c0 = INT_MAX, c1 = INT_MAX, c2c = INT_MAX, c3 = INT_MAX;
#pragma unroll
            for (int i = 7; i >= 0; i--) {
                if (__float_as_uint(mind[i])      == vb) c0  = i * NTHREADS + tid;
                if (__float_as_uint(mind[i + 8])  == vb) c1  = (i + 8) * NTHREADS + tid;
                if (__float_as_uint(mind[i + 16]) == vb) c2c = (i + 16) * NTHREADS + tid;
                if (__float_as_uint(mind[i + 24]) == vb) c3  = (i + 24) * NTHREADS + tid;
            }
            cand = min(min(c0, c1), min(c2c, c3));
        }
        int wmin_idx = __reduce_min_sync(0xffffffffu, cand);
        if (lane == 0) {
            s_wmax[buf * 8 + warp] = wmax;
            s_widx[buf * 8 + warp] = wmin_idx;
        }
        __syncthreads();  // single barrier per iteration

        // Stage B: every warp redundantly reduces across the 8 warp results.
        // Lanes 8..31 mirror lanes 0..7 (same data) — harmless for max/min.
        unsigned wv   = s_wmax[buf * 8 + (lane & 7)];
        unsigned gmax = __reduce_max_sync(0xffffffffu, wv);
        int c2 = (wv == gmax) ? s_widx[buf * 8 + (lane & 7)] : INT_MAX;
        gidx   = __reduce_min_sync(0xffffffffu, c2);

        if (tid == 0) s_idx[step] = gidx;   // 1 predicated STS
        buf ^= 1;                           // double-buffer: next step uses other slots
    }
    __syncthreads();  // s_idx complete

    // Batched writeout of indices + selected points (off the critical loop).
    for (int r = tid; r < MSEL; r += NTHREADS) {
        int id = s_idx[r];
        g_sel_idx[b * MSEL + r] = id;
        size_t o = ((size_t)b * MSEL + r) * 3;
        dp_out[o + 0] = s_pos2[6 * id + 0];
        dp_out[o + 1] = s_pos2[6 * id + 2];
        dp_out[o + 2] = s_pos2[6 * id + 4];
    }
}

// ---------------- Feature gather: [B, m, 256] float32 ----------------
__global__ void gather_kernel(const float* __restrict__ feat, float* __restrict__ df_out)
{
    // 256 threads/block -> 4 rows/block, 64 threads (float4 x 64 = 256 floats) per row.
    int r = blockIdx.x * 4 + (threadIdx.x >> 6);
    int c = threadIdx.x & 63;
    int b = r >> 12;  // r / 4096
    int id = g_sel_idx[r];
    const float4* src = (const float4*)(feat + ((size_t)b * NPTS + id) * 256);
    float4 v = src[c];
    ((float4*)df_out)[(size_t)r * 64 + c] = v;
}

extern "C" void kernel_launch(void* const* d_in, const int* in_sizes, int n_in,
                              void* d_out, int out_size)
{
    (void)n_in; (void)out_size;
    const float* points;
    const float* feats;
    if (in_sizes[0] == BATCH * NPTS * 3) {
        points = (const float*)d_in[0];
        feats  = (const float*)d_in[1];
    } else {
        points = (const float*)d_in[1];
        feats  = (const float*)d_in[0];
    }

    float* out = (float*)d_out;
    float* dp  = out;                              // [B, m, 3]
    float* df  = out + (size_t)BATCH * MSEL * 3;   // [B, m, 256]

    cudaFuncSetAttribute(fps_kernel, cudaFuncAttributeMaxDynamicSharedMemorySize,
                         SMEM_BYTES);
    fps_kernel<<<BATCH, NTHREADS, SMEM_BYTES>>>(points, dp);
    gather_kernel<<<(BATCH * MSEL) / 4, 256>>>(feats, df);
}